// round 6
// baseline (speedup 1.0000x reference)
#include <cuda_runtime.h>
#include <cstdint>

#define BATCH 16
#define CDIM 128
#define NTOK 16384
#define NHEADS 8
#define HDIM 16
#define PCH 16
#define KC (NTOK / PCH)   // 1024

// ---------------- scratch (static device globals; no allocations) ----------
__device__ float g_Gpart[BATCH * PCH * CDIM * CDIM]; // ~16.8 MB
__device__ float g_spart[BATCH * PCH * CDIM];
__device__ float g_G[BATCH * CDIM * CDIM];
__device__ float g_s[BATCH * CDIM];
__device__ float g_T[BATCH * CDIM * CDIM];
__device__ float g_u[BATCH * CDIM];
__device__ float g_M[BATCH * CDIM * CDIM];           // tf32-rounded values
__device__ float g_cv[BATCH * CDIM];

// ---------------- helpers ---------------------------------------------------
__device__ __forceinline__ uint32_t f2tf32u(float x) {
    uint32_t r;
    asm("cvt.rna.tf32.f32 %0, %1;" : "=r"(r) : "f"(x));
    return r;
}

__device__ __forceinline__ void mma_tf32(float& d0, float& d1, float& d2, float& d3,
                                         uint32_t a0, uint32_t a1, uint32_t a2, uint32_t a3,
                                         uint32_t b0, uint32_t b1) {
    asm volatile(
        "mma.sync.aligned.m16n8k8.row.col.f32.tf32.tf32.f32 "
        "{%0,%1,%2,%3}, {%4,%5,%6,%7}, {%8,%9}, {%0,%1,%2,%3};"
        : "+f"(d0), "+f"(d1), "+f"(d2), "+f"(d3)
        : "r"(a0), "r"(a1), "r"(a2), "r"(a3), "r"(b0), "r"(b1));
}

// ---------------- kernel 1: partial Gram G = X X^T (tf32 MMA) --------------
// grid (PCH, BATCH), block 256. Each CTA: 128x128 output over a 1024-wide K chunk.
__global__ __launch_bounds__(256) void k_gram(const float* __restrict__ x) {
    __shared__ float Xs[CDIM * 36];  // 128 rows x 32 k, stride 36 (pad 4)
    const int b = blockIdx.y, p = blockIdx.x;
    const int tid = threadIdx.x;
    const int lane = tid & 31, warp = tid >> 5;
    const int gid = lane >> 2, tig = lane & 3;
    const int mbase = (warp >> 2) * 64, nbase = (warp & 3) * 32;
    const float* xb = x + (size_t)b * CDIM * NTOK;

    float acc[4][4][4];
#pragma unroll
    for (int i = 0; i < 4; i++)
#pragma unroll
        for (int j = 0; j < 4; j++)
#pragma unroll
            for (int q = 0; q < 4; q++) acc[i][j][q] = 0.f;

    const int k0base = p * KC;
    for (int kt = 0; kt < KC / 32; kt++) {
        const int k0 = k0base + kt * 32;
        // cooperative load of 128x32 tile (tf32-rounded)
#pragma unroll
        for (int pass = 0; pass < 4; pass++) {
            const int c = pass * 32 + (tid >> 3);
            const int kslot = tid & 7;
            float4 v = *reinterpret_cast<const float4*>(xb + (size_t)c * NTOK + k0 + kslot * 4);
            v.x = __uint_as_float(f2tf32u(v.x));
            v.y = __uint_as_float(f2tf32u(v.y));
            v.z = __uint_as_float(f2tf32u(v.z));
            v.w = __uint_as_float(f2tf32u(v.w));
            *reinterpret_cast<float4*>(&Xs[c * 36 + kslot * 4]) = v;
        }
        __syncthreads();
#pragma unroll
        for (int ks = 0; ks < 4; ks++) {
            const int kb = ks * 8;
            uint32_t af[4][4], bf[4][2];
#pragma unroll
            for (int i = 0; i < 4; i++) {
                const int m = mbase + i * 16 + gid;
                af[i][0] = __float_as_uint(Xs[m * 36 + kb + tig]);
                af[i][1] = __float_as_uint(Xs[(m + 8) * 36 + kb + tig]);
                af[i][2] = __float_as_uint(Xs[m * 36 + kb + tig + 4]);
                af[i][3] = __float_as_uint(Xs[(m + 8) * 36 + kb + tig + 4]);
            }
#pragma unroll
            for (int j = 0; j < 4; j++) {
                const int n = nbase + j * 8 + gid;
                bf[j][0] = __float_as_uint(Xs[n * 36 + kb + tig]);
                bf[j][1] = __float_as_uint(Xs[n * 36 + kb + tig + 4]);
            }
#pragma unroll
            for (int i = 0; i < 4; i++)
#pragma unroll
                for (int j = 0; j < 4; j++)
                    mma_tf32(acc[i][j][0], acc[i][j][1], acc[i][j][2], acc[i][j][3],
                             af[i][0], af[i][1], af[i][2], af[i][3], bf[j][0], bf[j][1]);
        }
        __syncthreads();
    }

    // write partial G
    float* gp = g_Gpart + ((size_t)b * PCH + p) * CDIM * CDIM;
#pragma unroll
    for (int i = 0; i < 4; i++) {
        const int r0 = mbase + i * 16 + gid;
#pragma unroll
        for (int j = 0; j < 4; j++) {
            const int c0 = nbase + j * 8 + tig * 2;
            *reinterpret_cast<float2*>(&gp[r0 * CDIM + c0]) =
                make_float2(acc[i][j][0], acc[i][j][1]);
            *reinterpret_cast<float2*>(&gp[(r0 + 8) * CDIM + c0]) =
                make_float2(acc[i][j][2], acc[i][j][3]);
        }
    }

    // partial row sums s = X @ 1 over this K chunk (exact fp32 from global)
    const int r = tid >> 1;
    const float* row = xb + (size_t)r * NTOK + k0base + (tid & 1) * 512;
    float sum = 0.f;
    for (int k = 0; k < 512; k += 4) {
        float4 v = *reinterpret_cast<const float4*>(row + k);
        sum += v.x + v.y + v.z + v.w;
    }
    sum += __shfl_xor_sync(0xffffffffu, sum, 1);
    if (!(tid & 1)) g_spart[((size_t)b * PCH + p) * CDIM + r] = sum;
}

// ---------------- kernel 2: reduce partials --------------------------------
// grid (8, BATCH), block 256
__global__ __launch_bounds__(256) void k_reduceG() {
    const int b = blockIdx.y;
    const int base = blockIdx.x * 2048;
    for (int idx = base + threadIdx.x; idx < base + 2048; idx += 256) {
        float s = 0.f;
#pragma unroll
        for (int p = 0; p < PCH; p++)
            s += g_Gpart[((size_t)b * PCH + p) * CDIM * CDIM + idx];
        g_G[(size_t)b * CDIM * CDIM + idx] = s;
    }
    if (blockIdx.x == 0 && threadIdx.x < CDIM) {
        float s = 0.f;
#pragma unroll
        for (int p = 0; p < PCH; p++)
            s += g_spart[((size_t)b * PCH + p) * CDIM + threadIdx.x];
        g_s[b * CDIM + threadIdx.x] = s;
    }
}

// ---------------- kernel 3: per-(batch,head) scores/softmax/T --------------
// grid (NHEADS, BATCH), block 256
__global__ __launch_bounds__(256) void k_attn(const float* __restrict__ w_qkv,
                                              const float* __restrict__ b_qkv) {
    __shared__ float Rs[HDIM][CDIM];
    __shared__ float Ss[HDIM][HDIM];
    __shared__ float qs[HDIM], kssum[HDIM];
    const int h = blockIdx.x, b = blockIdx.y;
    const int tid = threadIdx.x;
    const int d = tid >> 4, cg = tid & 15;
    const float* G = g_G + (size_t)b * CDIM * CDIM;
    const float* Wq = w_qkv + (size_t)(h * HDIM) * CDIM;
    const float* Wk = w_qkv + (size_t)(CDIM + h * HDIM) * CDIM;
    const float* Wv = w_qkv + (size_t)(2 * CDIM + h * HDIM) * CDIM;

    // qs[d] = Wq_h s, kssum[e] = Wk_h s
    if (tid < 2 * HDIM) {
        const int dd = tid & 15;
        const float* W = (tid < HDIM) ? Wq : Wk;
        float acc = 0.f;
        for (int c = 0; c < CDIM; c++) acc += W[dd * CDIM + c] * g_s[b * CDIM + c];
        if (tid < HDIM) qs[dd] = acc; else kssum[dd] = acc;
    }

    // R = Wq_h @ G  (16x128)
    {
        float a[8] = {0, 0, 0, 0, 0, 0, 0, 0};
        for (int c = 0; c < CDIM; c++) {
            const float wq = __ldg(&Wq[d * CDIM + c]);
            const float4* gp = reinterpret_cast<const float4*>(G + c * CDIM + cg * 8);
            const float4 g0 = __ldg(gp), g1 = __ldg(gp + 1);
            a[0] += wq * g0.x; a[1] += wq * g0.y; a[2] += wq * g0.z; a[3] += wq * g0.w;
            a[4] += wq * g1.x; a[5] += wq * g1.y; a[6] += wq * g1.z; a[7] += wq * g1.w;
        }
#pragma unroll
        for (int j = 0; j < 8; j++) Rs[d][cg * 8 + j] = a[j];
    }
    __syncthreads();

    // scores[d][e] = (R Wk^T + rank-1 bias terms) / sqrt(C)
    {
        const int e = cg;
        float acc = 0.f;
        for (int c = 0; c < CDIM; c++) acc += Rs[d][c] * __ldg(&Wk[e * CDIM + c]);
        const float bq = b_qkv[h * HDIM + d];
        const float bk = b_qkv[CDIM + h * HDIM + e];
        acc += qs[d] * bk + bq * kssum[e] + (float)NTOK * bq * bk;
        Ss[d][e] = acc * 0.08838834764831845f;  // 1/sqrt(128)
    }
    __syncthreads();

    // softmax rows (16 threads, one row each)
    if (tid < HDIM) {
        float m = -1e30f;
#pragma unroll
        for (int e = 0; e < HDIM; e++) m = fmaxf(m, Ss[tid][e]);
        float ex[HDIM], sum = 0.f;
#pragma unroll
        for (int e = 0; e < HDIM; e++) { ex[e] = expf(Ss[tid][e] - m); sum += ex[e]; }
        const float inv = 1.f / sum;
#pragma unroll
        for (int e = 0; e < HDIM; e++) Ss[tid][e] = ex[e] * inv;
    }
    __syncthreads();

    // T_h = A_h @ Wv_h (16x128) -> g_T row (h*16+d)
    {
        float a[8] = {0, 0, 0, 0, 0, 0, 0, 0};
#pragma unroll
        for (int e = 0; e < HDIM; e++) {
            const float av = Ss[d][e];
            const float4* vp = reinterpret_cast<const float4*>(Wv + e * CDIM + cg * 8);
            const float4 v0 = __ldg(vp), v1 = __ldg(vp + 1);
            a[0] += av * v0.x; a[1] += av * v0.y; a[2] += av * v0.z; a[3] += av * v0.w;
            a[4] += av * v1.x; a[5] += av * v1.y; a[6] += av * v1.z; a[7] += av * v1.w;
        }
        float* Tp = g_T + (size_t)b * CDIM * CDIM + (h * HDIM + d) * CDIM + cg * 8;
        *reinterpret_cast<float4*>(Tp) = make_float4(a[0], a[1], a[2], a[3]);
        *reinterpret_cast<float4*>(Tp + 4) = make_float4(a[4], a[5], a[6], a[7]);
    }
    // u_h = A_h @ bv_h
    if (tid < HDIM) {
        float u = 0.f;
#pragma unroll
        for (int e = 0; e < HDIM; e++) u += Ss[tid][e] * b_qkv[2 * CDIM + h * HDIM + e];
        g_u[b * CDIM + h * HDIM + tid] = u;
    }
}

// ---------------- kernel 4: M = W_out @ T (tf32-rounded), cvec -------------
// grid (8, BATCH), block 256
__global__ __launch_bounds__(256) void k_mout(const float* __restrict__ w_out,
                                              const float* __restrict__ b_out) {
    const int b = blockIdx.y;
    const int o = blockIdx.x * 16 + (threadIdx.x >> 4);
    const int cg = threadIdx.x & 15;
    const float* T = g_T + (size_t)b * CDIM * CDIM;
    float a[8] = {0, 0, 0, 0, 0, 0, 0, 0};
    for (int j = 0; j < CDIM; j++) {
        const float wo = __ldg(&w_out[o * CDIM + j]);
        const float4* tp = reinterpret_cast<const float4*>(T + j * CDIM + cg * 8);
        const float4 t0 = __ldg(tp), t1 = __ldg(tp + 1);
        a[0] += wo * t0.x; a[1] += wo * t0.y; a[2] += wo * t0.z; a[3] += wo * t0.w;
        a[4] += wo * t1.x; a[5] += wo * t1.y; a[6] += wo * t1.z; a[7] += wo * t1.w;
    }
    float* Mp = g_M + (size_t)b * CDIM * CDIM + o * CDIM + cg * 8;
#pragma unroll
    for (int j = 0; j < 8; j++) Mp[j] = __uint_as_float(f2tf32u(a[j]));

    if (blockIdx.x == 0 && threadIdx.x < CDIM) {
        const int oo = threadIdx.x;
        float acc = b_out[oo];
        for (int j = 0; j < CDIM; j++) acc += w_out[oo * CDIM + j] * g_u[b * CDIM + j];
        g_cv[b * CDIM + oo] = acc;
    }
}

// ---------------- kernel 5: final = M @ X + c (tf32 MMA) -------------------
// grid (NTOK/128, BATCH), block 256. CTA tile 128(m) x 128(n), K=128.
__global__ __launch_bounds__(256) void k_final(const float* __restrict__ x,
                                               float* __restrict__ out) {
    __shared__ float Xs[64 * 132];
    const int b = blockIdx.y;
    const int n0 = blockIdx.x * 128;
    const int tid = threadIdx.x;
    const int lane = tid & 31, warp = tid >> 5;
    const int gid = lane >> 2, tig = lane & 3;
    const int mbase = (warp >> 2) * 64, nbase = (warp & 3) * 32;
    const float* xb = x + (size_t)b * CDIM * NTOK;
    const float* Mb = g_M + (size_t)b * CDIM * CDIM;

    float acc[4][4][4];
#pragma unroll
    for (int i = 0; i < 4; i++)
#pragma unroll
        for (int j = 0; j < 4; j++)
#pragma unroll
            for (int q = 0; q < 4; q++) acc[i][j][q] = 0.f;

    for (int kp = 0; kp < 2; kp++) {
        // load X[kp*64 .. +64][n0 .. n0+128] (tf32-rounded)
#pragma unroll
        for (int pass = 0; pass < 8; pass++) {
            const int r = pass * 8 + (tid >> 5);
            const int slot = tid & 31;
            float4 v = *reinterpret_cast<const float4*>(
                xb + (size_t)(kp * 64 + r) * NTOK + n0 + slot * 4);
            v.x = __uint_as_float(f2tf32u(v.x));
            v.y = __uint_as_float(f2tf32u(v.y));
            v.z = __uint_as_float(f2tf32u(v.z));
            v.w = __uint_as_float(f2tf32u(v.w));
            *reinterpret_cast<float4*>(&Xs[r * 132 + slot * 4]) = v;
        }
        __syncthreads();
#pragma unroll
        for (int ks = 0; ks < 8; ks++) {
            const int kb = ks * 8;
            const int kglob = kp * 64 + kb;
            uint32_t af[4][4], bf[4][2];
#pragma unroll
            for (int i = 0; i < 4; i++) {
                const int m = mbase + i * 16 + gid;
                af[i][0] = __float_as_uint(__ldg(&Mb[m * CDIM + kglob + tig]));
                af[i][1] = __float_as_uint(__ldg(&Mb[(m + 8) * CDIM + kglob + tig]));
                af[i][2] = __float_as_uint(__ldg(&Mb[m * CDIM + kglob + tig + 4]));
                af[i][3] = __float_as_uint(__ldg(&Mb[(m + 8) * CDIM + kglob + tig + 4]));
            }
#pragma unroll
            for (int j = 0; j < 4; j++) {
                const int n = nbase + j * 8 + gid;
                bf[j][0] = __float_as_uint(Xs[(kb + tig) * 132 + n]);
                bf[j][1] = __float_as_uint(Xs[(kb + tig + 4) * 132 + n]);
            }
#pragma unroll
            for (int i = 0; i < 4; i++)
#pragma unroll
                for (int j = 0; j < 4; j++)
                    mma_tf32(acc[i][j][0], acc[i][j][1], acc[i][j][2], acc[i][j][3],
                             af[i][0], af[i][1], af[i][2], af[i][3], bf[j][0], bf[j][1]);
        }
        __syncthreads();
    }

    // epilogue: + cvec, write out
#pragma unroll
    for (int i = 0; i < 4; i++) {
        const int r0 = mbase + i * 16 + gid;
        const float cv0 = g_cv[b * CDIM + r0];
        const float cv1 = g_cv[b * CDIM + r0 + 8];
        float* op0 = out + ((size_t)b * CDIM + r0) * NTOK + n0;
        float* op1 = op0 + (size_t)8 * NTOK;
#pragma unroll
        for (int j = 0; j < 4; j++) {
            const int c0 = nbase + j * 8 + tig * 2;
            *reinterpret_cast<float2*>(op0 + c0) =
                make_float2(acc[i][j][0] + cv0, acc[i][j][1] + cv0);
            *reinterpret_cast<float2*>(op1 + c0) =
                make_float2(acc[i][j][2] + cv1, acc[i][j][3] + cv1);
        }
    }
}

// ---------------- launch -----------------------------------------------------
extern "C" void kernel_launch(void* const* d_in, const int* in_sizes, int n_in,
                              void* d_out, int out_size) {
    (void)in_sizes; (void)n_in; (void)out_size;
    const float* x     = (const float*)d_in[0];
    const float* w_qkv = (const float*)d_in[1];
    const float* b_qkv = (const float*)d_in[2];
    const float* w_out = (const float*)d_in[3];
    const float* b_out = (const float*)d_in[4];
    float* out = (float*)d_out;

    k_gram<<<dim3(PCH, BATCH), 256>>>(x);
    k_reduceG<<<dim3(8, BATCH), 256>>>();
    k_attn<<<dim3(NHEADS, BATCH), 256>>>(w_qkv, b_qkv);
    k_mout<<<dim3(8, BATCH), 256>>>(w_out, b_out);
    k_final<<<dim3(NTOK / 128, BATCH), 256>>>(x, out);
}

// round 7
// speedup vs baseline: 1.0007x; 1.0007x over previous
#include <cuda_runtime.h>
#include <cstdint>

#define BATCH 16
#define CDIM 128
#define NTOK 16384
#define NHEADS 8
#define HDIM 16
#define PCH 16
#define KC (NTOK / PCH)   // 1024

// ---------------- scratch (static device globals; no allocations) ----------
__device__ float g_Gpart[BATCH * PCH * CDIM * CDIM]; // ~16.8 MB
__device__ float g_spart[BATCH * PCH * CDIM];
__device__ float g_G[BATCH * CDIM * CDIM];
__device__ float g_s[BATCH * CDIM];
__device__ float g_T[BATCH * CDIM * CDIM];
__device__ float g_u[BATCH * CDIM];
__device__ float g_M[BATCH * CDIM * CDIM];           // tf32-rounded values
__device__ float g_cv[BATCH * CDIM];

// ---------------- helpers ---------------------------------------------------
__device__ __forceinline__ uint32_t f2tf32u(float x) {
    uint32_t r;
    asm("cvt.rna.tf32.f32 %0, %1;" : "=r"(r) : "f"(x));
    return r;
}

__device__ __forceinline__ void mma_tf32(float& d0, float& d1, float& d2, float& d3,
                                         uint32_t a0, uint32_t a1, uint32_t a2, uint32_t a3,
                                         uint32_t b0, uint32_t b1) {
    asm volatile(
        "mma.sync.aligned.m16n8k8.row.col.f32.tf32.tf32.f32 "
        "{%0,%1,%2,%3}, {%4,%5,%6,%7}, {%8,%9}, {%0,%1,%2,%3};"
        : "+f"(d0), "+f"(d1), "+f"(d2), "+f"(d3)
        : "r"(a0), "r"(a1), "r"(a2), "r"(a3), "r"(b0), "r"(b1));
}

// ---------------- kernel 1: partial Gram G = X X^T (tf32 MMA) --------------
// grid (PCH, BATCH), block 256. Each CTA: 128x128 output over a 1024-wide K chunk.
__global__ __launch_bounds__(256) void k_gram(const float* __restrict__ x) {
    __shared__ float Xs[CDIM * 36];  // 128 rows x 32 k, stride 36 (pad 4)
    const int b = blockIdx.y, p = blockIdx.x;
    const int tid = threadIdx.x;
    const int lane = tid & 31, warp = tid >> 5;
    const int gid = lane >> 2, tig = lane & 3;
    const int mbase = (warp >> 2) * 64, nbase = (warp & 3) * 32;
    const float* xb = x + (size_t)b * CDIM * NTOK;

    float acc[4][4][4];
#pragma unroll
    for (int i = 0; i < 4; i++)
#pragma unroll
        for (int j = 0; j < 4; j++)
#pragma unroll
            for (int q = 0; q < 4; q++) acc[i][j][q] = 0.f;

    const int k0base = p * KC;
    for (int kt = 0; kt < KC / 32; kt++) {
        const int k0 = k0base + kt * 32;
        // cooperative load of 128x32 tile (tf32-rounded)
#pragma unroll
        for (int pass = 0; pass < 4; pass++) {
            const int c = pass * 32 + (tid >> 3);
            const int kslot = tid & 7;
            float4 v = *reinterpret_cast<const float4*>(xb + (size_t)c * NTOK + k0 + kslot * 4);
            v.x = __uint_as_float(f2tf32u(v.x));
            v.y = __uint_as_float(f2tf32u(v.y));
            v.z = __uint_as_float(f2tf32u(v.z));
            v.w = __uint_as_float(f2tf32u(v.w));
            *reinterpret_cast<float4*>(&Xs[c * 36 + kslot * 4]) = v;
        }
        __syncthreads();
#pragma unroll
        for (int ks = 0; ks < 4; ks++) {
            const int kb = ks * 8;
            uint32_t af[4][4], bf[4][2];
#pragma unroll
            for (int i = 0; i < 4; i++) {
                const int m = mbase + i * 16 + gid;
                af[i][0] = __float_as_uint(Xs[m * 36 + kb + tig]);
                af[i][1] = __float_as_uint(Xs[(m + 8) * 36 + kb + tig]);
                af[i][2] = __float_as_uint(Xs[m * 36 + kb + tig + 4]);
                af[i][3] = __float_as_uint(Xs[(m + 8) * 36 + kb + tig + 4]);
            }
#pragma unroll
            for (int j = 0; j < 4; j++) {
                const int n = nbase + j * 8 + gid;
                bf[j][0] = __float_as_uint(Xs[n * 36 + kb + tig]);
                bf[j][1] = __float_as_uint(Xs[n * 36 + kb + tig + 4]);
            }
#pragma unroll
            for (int i = 0; i < 4; i++)
#pragma unroll
                for (int j = 0; j < 4; j++)
                    mma_tf32(acc[i][j][0], acc[i][j][1], acc[i][j][2], acc[i][j][3],
                             af[i][0], af[i][1], af[i][2], af[i][3], bf[j][0], bf[j][1]);
        }
        __syncthreads();
    }

    // write partial G
    float* gp = g_Gpart + ((size_t)b * PCH + p) * CDIM * CDIM;
#pragma unroll
    for (int i = 0; i < 4; i++) {
        const int r0 = mbase + i * 16 + gid;
#pragma unroll
        for (int j = 0; j < 4; j++) {
            const int c0 = nbase + j * 8 + tig * 2;
            *reinterpret_cast<float2*>(&gp[r0 * CDIM + c0]) =
                make_float2(acc[i][j][0], acc[i][j][1]);
            *reinterpret_cast<float2*>(&gp[(r0 + 8) * CDIM + c0]) =
                make_float2(acc[i][j][2], acc[i][j][3]);
        }
    }

    // partial row sums s = X @ 1 over this K chunk (exact fp32 from global)
    const int r = tid >> 1;
    const float* row = xb + (size_t)r * NTOK + k0base + (tid & 1) * 512;
    float sum = 0.f;
    for (int k = 0; k < 512; k += 4) {
        float4 v = *reinterpret_cast<const float4*>(row + k);
        sum += v.x + v.y + v.z + v.w;
    }
    sum += __shfl_xor_sync(0xffffffffu, sum, 1);
    if (!(tid & 1)) g_spart[((size_t)b * PCH + p) * CDIM + r] = sum;
}

// ---------------- kernel 2: reduce partials --------------------------------
// grid (8, BATCH), block 256
__global__ __launch_bounds__(256) void k_reduceG() {
    const int b = blockIdx.y;
    const int base = blockIdx.x * 2048;
    for (int idx = base + threadIdx.x; idx < base + 2048; idx += 256) {
        float s = 0.f;
#pragma unroll
        for (int p = 0; p < PCH; p++)
            s += g_Gpart[((size_t)b * PCH + p) * CDIM * CDIM + idx];
        g_G[(size_t)b * CDIM * CDIM + idx] = s;
    }
    if (blockIdx.x == 0 && threadIdx.x < CDIM) {
        float s = 0.f;
#pragma unroll
        for (int p = 0; p < PCH; p++)
            s += g_spart[((size_t)b * PCH + p) * CDIM + threadIdx.x];
        g_s[b * CDIM + threadIdx.x] = s;
    }
}

// ---------------- kernel 3: per-(batch,head) scores/softmax/T --------------
// grid (NHEADS, BATCH), block 256
__global__ __launch_bounds__(256) void k_attn(const float* __restrict__ w_qkv,
                                              const float* __restrict__ b_qkv) {
    __shared__ float Rs[HDIM][CDIM];
    __shared__ float Ss[HDIM][HDIM];
    __shared__ float qs[HDIM], kssum[HDIM];
    const int h = blockIdx.x, b = blockIdx.y;
    const int tid = threadIdx.x;
    const int d = tid >> 4, cg = tid & 15;
    const float* G = g_G + (size_t)b * CDIM * CDIM;
    const float* Wq = w_qkv + (size_t)(h * HDIM) * CDIM;
    const float* Wk = w_qkv + (size_t)(CDIM + h * HDIM) * CDIM;
    const float* Wv = w_qkv + (size_t)(2 * CDIM + h * HDIM) * CDIM;

    // qs[d] = Wq_h s, kssum[e] = Wk_h s
    if (tid < 2 * HDIM) {
        const int dd = tid & 15;
        const float* W = (tid < HDIM) ? Wq : Wk;
        float acc = 0.f;
        for (int c = 0; c < CDIM; c++) acc += W[dd * CDIM + c] * g_s[b * CDIM + c];
        if (tid < HDIM) qs[dd] = acc; else kssum[dd] = acc;
    }

    // R = Wq_h @ G  (16x128)
    {
        float a[8] = {0, 0, 0, 0, 0, 0, 0, 0};
        for (int c = 0; c < CDIM; c++) {
            const float wq = __ldg(&Wq[d * CDIM + c]);
            const float4* gp = reinterpret_cast<const float4*>(G + c * CDIM + cg * 8);
            const float4 g0 = __ldg(gp), g1 = __ldg(gp + 1);
            a[0] += wq * g0.x; a[1] += wq * g0.y; a[2] += wq * g0.z; a[3] += wq * g0.w;
            a[4] += wq * g1.x; a[5] += wq * g1.y; a[6] += wq * g1.z; a[7] += wq * g1.w;
        }
#pragma unroll
        for (int j = 0; j < 8; j++) Rs[d][cg * 8 + j] = a[j];
    }
    __syncthreads();

    // scores[d][e] = (R Wk^T + rank-1 bias terms) / sqrt(C)
    {
        const int e = cg;
        float acc = 0.f;
        for (int c = 0; c < CDIM; c++) acc += Rs[d][c] * __ldg(&Wk[e * CDIM + c]);
        const float bq = b_qkv[h * HDIM + d];
        const float bk = b_qkv[CDIM + h * HDIM + e];
        acc += qs[d] * bk + bq * kssum[e] + (float)NTOK * bq * bk;
        Ss[d][e] = acc * 0.08838834764831845f;  // 1/sqrt(128)
    }
    __syncthreads();

    // softmax rows (16 threads, one row each)
    if (tid < HDIM) {
        float m = -1e30f;
#pragma unroll
        for (int e = 0; e < HDIM; e++) m = fmaxf(m, Ss[tid][e]);
        float ex[HDIM], sum = 0.f;
#pragma unroll
        for (int e = 0; e < HDIM; e++) { ex[e] = expf(Ss[tid][e] - m); sum += ex[e]; }
        const float inv = 1.f / sum;
#pragma unroll
        for (int e = 0; e < HDIM; e++) Ss[tid][e] = ex[e] * inv;
    }
    __syncthreads();

    // T_h = A_h @ Wv_h (16x128) -> g_T row (h*16+d)
    {
        float a[8] = {0, 0, 0, 0, 0, 0, 0, 0};
#pragma unroll
        for (int e = 0; e < HDIM; e++) {
            const float av = Ss[d][e];
            const float4* vp = reinterpret_cast<const float4*>(Wv + e * CDIM + cg * 8);
            const float4 v0 = __ldg(vp), v1 = __ldg(vp + 1);
            a[0] += av * v0.x; a[1] += av * v0.y; a[2] += av * v0.z; a[3] += av * v0.w;
            a[4] += av * v1.x; a[5] += av * v1.y; a[6] += av * v1.z; a[7] += av * v1.w;
        }
        float* Tp = g_T + (size_t)b * CDIM * CDIM + (h * HDIM + d) * CDIM + cg * 8;
        *reinterpret_cast<float4*>(Tp) = make_float4(a[0], a[1], a[2], a[3]);
        *reinterpret_cast<float4*>(Tp + 4) = make_float4(a[4], a[5], a[6], a[7]);
    }
    // u_h = A_h @ bv_h
    if (tid < HDIM) {
        float u = 0.f;
#pragma unroll
        for (int e = 0; e < HDIM; e++) u += Ss[tid][e] * b_qkv[2 * CDIM + h * HDIM + e];
        g_u[b * CDIM + h * HDIM + tid] = u;
    }
}

// ---------------- kernel 4: M = W_out @ T (tf32-rounded), cvec -------------
// grid (8, BATCH), block 256
__global__ __launch_bounds__(256) void k_mout(const float* __restrict__ w_out,
                                              const float* __restrict__ b_out) {
    const int b = blockIdx.y;
    const int o = blockIdx.x * 16 + (threadIdx.x >> 4);
    const int cg = threadIdx.x & 15;
    const float* T = g_T + (size_t)b * CDIM * CDIM;
    float a[8] = {0, 0, 0, 0, 0, 0, 0, 0};
    for (int j = 0; j < CDIM; j++) {
        const float wo = __ldg(&w_out[o * CDIM + j]);
        const float4* tp = reinterpret_cast<const float4*>(T + j * CDIM + cg * 8);
        const float4 t0 = __ldg(tp), t1 = __ldg(tp + 1);
        a[0] += wo * t0.x; a[1] += wo * t0.y; a[2] += wo * t0.z; a[3] += wo * t0.w;
        a[4] += wo * t1.x; a[5] += wo * t1.y; a[6] += wo * t1.z; a[7] += wo * t1.w;
    }
    float* Mp = g_M + (size_t)b * CDIM * CDIM + o * CDIM + cg * 8;
#pragma unroll
    for (int j = 0; j < 8; j++) Mp[j] = __uint_as_float(f2tf32u(a[j]));

    if (blockIdx.x == 0 && threadIdx.x < CDIM) {
        const int oo = threadIdx.x;
        float acc = b_out[oo];
        for (int j = 0; j < CDIM; j++) acc += w_out[oo * CDIM + j] * g_u[b * CDIM + j];
        g_cv[b * CDIM + oo] = acc;
    }
}

// ---------------- kernel 5: final = M @ X + c (tf32 MMA) -------------------
// grid (NTOK/128, BATCH), block 256. CTA tile 128(m) x 128(n), K=128.
__global__ __launch_bounds__(256) void k_final(const float* __restrict__ x,
                                               float* __restrict__ out) {
    __shared__ float Xs[64 * 132];
    const int b = blockIdx.y;
    const int n0 = blockIdx.x * 128;
    const int tid = threadIdx.x;
    const int lane = tid & 31, warp = tid >> 5;
    const int gid = lane >> 2, tig = lane & 3;
    const int mbase = (warp >> 2) * 64, nbase = (warp & 3) * 32;
    const float* xb = x + (size_t)b * CDIM * NTOK;
    const float* Mb = g_M + (size_t)b * CDIM * CDIM;

    float acc[4][4][4];
#pragma unroll
    for (int i = 0; i < 4; i++)
#pragma unroll
        for (int j = 0; j < 4; j++)
#pragma unroll
            for (int q = 0; q < 4; q++) acc[i][j][q] = 0.f;

    for (int kp = 0; kp < 2; kp++) {
        // load X[kp*64 .. +64][n0 .. n0+128] (tf32-rounded)
#pragma unroll
        for (int pass = 0; pass < 8; pass++) {
            const int r = pass * 8 + (tid >> 5);
            const int slot = tid & 31;
            float4 v = *reinterpret_cast<const float4*>(
                xb + (size_t)(kp * 64 + r) * NTOK + n0 + slot * 4);
            v.x = __uint_as_float(f2tf32u(v.x));
            v.y = __uint_as_float(f2tf32u(v.y));
            v.z = __uint_as_float(f2tf32u(v.z));
            v.w = __uint_as_float(f2tf32u(v.w));
            *reinterpret_cast<float4*>(&Xs[r * 132 + slot * 4]) = v;
        }
        __syncthreads();
#pragma unroll
        for (int ks = 0; ks < 8; ks++) {
            const int kb = ks * 8;
            const int kglob = kp * 64 + kb;
            uint32_t af[4][4], bf[4][2];
#pragma unroll
            for (int i = 0; i < 4; i++) {
                const int m = mbase + i * 16 + gid;
                af[i][0] = __float_as_uint(__ldg(&Mb[m * CDIM + kglob + tig]));
                af[i][1] = __float_as_uint(__ldg(&Mb[(m + 8) * CDIM + kglob + tig]));
                af[i][2] = __float_as_uint(__ldg(&Mb[m * CDIM + kglob + tig + 4]));
                af[i][3] = __float_as_uint(__ldg(&Mb[(m + 8) * CDIM + kglob + tig + 4]));
            }
#pragma unroll
            for (int j = 0; j < 4; j++) {
                const int n = nbase + j * 8 + gid;
                bf[j][0] = __float_as_uint(Xs[(kb + tig) * 132 + n]);
                bf[j][1] = __float_as_uint(Xs[(kb + tig + 4) * 132 + n]);
            }
#pragma unroll
            for (int i = 0; i < 4; i++)
#pragma unroll
                for (int j = 0; j < 4; j++)
                    mma_tf32(acc[i][j][0], acc[i][j][1], acc[i][j][2], acc[i][j][3],
                             af[i][0], af[i][1], af[i][2], af[i][3], bf[j][0], bf[j][1]);
        }
        __syncthreads();
    }

    // epilogue: + cvec, write out
#pragma unroll
    for (int i = 0; i < 4; i++) {
        const int r0 = mbase + i * 16 + gid;
        const float cv0 = g_cv[b * CDIM + r0];
        const float cv1 = g_cv[b * CDIM + r0 + 8];
        float* op0 = out + ((size_t)b * CDIM + r0) * NTOK + n0;
        float* op1 = op0 + (size_t)8 * NTOK;
#pragma unroll
        for (int j = 0; j < 4; j++) {
            const int c0 = nbase + j * 8 + tig * 2;
            *reinterpret_cast<float2*>(op0 + c0) =
                make_float2(acc[i][j][0] + cv0, acc[i][j][1] + cv0);
            *reinterpret_cast<float2*>(op1 + c0) =
                make_float2(acc[i][j][2] + cv1, acc[i][j][3] + cv1);
        }
    }
}

// ---------------- launch -----------------------------------------------------
extern "C" void kernel_launch(void* const* d_in, const int* in_sizes, int n_in,
                              void* d_out, int out_size) {
    (void)in_sizes; (void)n_in; (void)out_size;
    const float* x     = (const float*)d_in[0];
    const float* w_qkv = (const float*)d_in[1];
    const float* b_qkv = (const float*)d_in[2];
    const float* w_out = (const float*)d_in[3];
    const float* b_out = (const float*)d_in[4];
    float* out = (float*)d_out;

    k_gram<<<dim3(PCH, BATCH), 256>>>(x);
    k_reduceG<<<dim3(8, BATCH), 256>>>();
    k_attn<<<dim3(NHEADS, BATCH), 256>>>(w_qkv, b_qkv);
    k_mout<<<dim3(8, BATCH), 256>>>(w_out, b_out);
    k_final<<<dim3(NTOK / 128, BATCH), 256>>>(x, out);
}